// round 2
// baseline (speedup 1.0000x reference)
#include <cuda_runtime.h>

// ---------------------------------------------------------------------------
// Faithful fp32 replication of the reference soft-arithmetic primitives.
// XLA expands logistic(x) as 0.5 + 0.5*tanh(0.5*x); tanh saturates to exactly
// +/-1.0f for |arg| >~ 9, which makes eq_gate an exact one-hot and makes
// out-of-window digit-gate terms exactly 0.0f. All arithmetic uses explicit
// round-to-nearest intrinsics so nvcc cannot FMA-contract and change rounding.
// ---------------------------------------------------------------------------

static __device__ __forceinline__ float sig_ref(float z) {
    return __fadd_rn(__fmul_rn(0.5f, tanhf(__fmul_rn(0.5f, z))), 0.5f);
}

static __device__ __forceinline__ float silu_ref(float z) {
    return __fmul_rn(z, sig_ref(z));
}

// silu_threshold(x) = (silu(20x + 10) - silu(20x - 10)) / 20
static __device__ __forceinline__ float st_ref(float x) {
    float d = __fmul_rn(20.0f, x);
    float a = silu_ref(__fadd_rn(d, 10.0f));
    float b = silu_ref(__fsub_rn(d, 10.0f));
    return __fdiv_rn(__fsub_rn(a, b), 20.0f);
}

__global__ void fill_zero_kernel(float* __restrict__ out, int n) {
    int i = blockIdx.x * blockDim.x + threadIdx.x;
    if (i < n) out[i] = 0.0f;
}

__global__ void c4_printf_kernel(const float* __restrict__ mem,
                                 const int*   __restrict__ addr,
                                 const int*   __restrict__ outp,
                                 float*       __restrict__ out,
                                 int B, int M) {
    int b = blockIdx.x * blockDim.x + threadIdx.x;
    if (b >= B) return;

    // --- soft memory attend collapses to an exact gather -------------------
    // eq_gate(i, addr) is bitwise {1 at i==addr, 0 elsewhere} under the
    // tanh-based sigmoid, so value == |memory[b, addr]| exactly.
    int a = addr[b];
    float v = fabsf(__ldg(mem + (long long)b * M + a));

    // --- _count_digits: 1 + sum_i st(v - 10^i + 0.5), i = 1..5 -------------
    float count = 1.0f;
    float p = 10.0f;
    #pragma unroll
    for (int i = 1; i < 6; ++i) {
        count = __fadd_rn(count, st_ref(__fadd_rn(__fsub_rn(v, p), 0.5f)));
        p = __fmul_rn(p, 10.0f);
    }
    int n = (int)floorf(count);

    // --- _get_digit for pos 0..5 -------------------------------------------
    // Terms q*lower*upper are exactly 0 unless both gate args > -1.5
    // (tanh saturation -> silu == exact 0). Window: q in
    // [(v-1.3)/d - 1, (v+2.3)/d + 1] with >= 1.3 units of slack beyond the
    // true -1.402 cutoff. <= ~7 live q's at pos 0, fewer above.
    float digits[6];
    const float dtab[6]   = {1.f, 10.f, 100.f, 1000.f, 10000.f, 100000.f};
    const int   qmaxtab[6] = {999, 101, 11, 2, 1, 1};

    #pragma unroll
    for (int pos = 0; pos < 6; ++pos) {
        float d = dtab[pos];
        int qmax = qmaxtab[pos];
        int qlo = (int)floorf((v - 1.3f) / d) - 1;
        int qhi = (int)floorf((v + 2.3f) / d) + 1;
        if (qlo < 0)    qlo = 0;
        if (qhi > qmax) qhi = qmax;

        float quot = 0.0f;
        for (int q = qlo; q <= qhi; ++q) {
            float qf = (float)q;
            // lower = st(v - q*d + 0.5)   (reference operand order)
            float lo_arg = __fadd_rn(__fsub_rn(v, __fmul_rn(qf, d)), 0.5f);
            // upper = st((q+1)*d - v - 0.5)
            float up_arg = __fsub_rn(
                __fsub_rn(__fmul_rn(__fadd_rn(qf, 1.0f), d), v), 0.5f);
            float lo = st_ref(lo_arg);
            float up = st_ref(up_arg);
            quot = __fadd_rn(quot, __fmul_rn(__fmul_rn(lo, up), qf));
        }
        // digit = floor(quot - floor(quot/10)*10)
        float dig = __fsub_rn(
            quot, __fmul_rn(floorf(__fdiv_rn(quot, 10.0f)), 10.0f));
        digits[pos] = floorf(dig);
    }

    // --- token assembly + scatter -------------------------------------------
    // tokens[j] = 48 + digits[clip(n-1-j,0,5)] for j < n; newline (10) at
    // j == n; positions out_ptr + j for j <= n, OOB (>=64) dropped.
    int op = outp[b];
    float* orow = out + (long long)b * 65;
    #pragma unroll
    for (int j = 0; j <= 6; ++j) {
        if (j <= n) {
            float tok;
            if (j < n) {
                int pi = n - 1 - j;
                pi = pi < 0 ? 0 : (pi > 5 ? 5 : pi);
                tok = __fadd_rn(48.0f, digits[pi]);
            } else {
                tok = 10.0f;
            }
            int wp = op + j;
            if (wp >= 0 && wp < 64) orow[wp] = tok;
        }
    }
    // last column = attended value
    orow[64] = v;
}

extern "C" void kernel_launch(void* const* d_in, const int* in_sizes, int n_in,
                              void* d_out, int out_size) {
    const float* mem  = (const float*)d_in[0];   // [B, M] fp32
    const int*   addr = (const int*)d_in[1];     // [B] int32
    const int*   outp = (const int*)d_in[2];     // [B] int32
    float*       out  = (float*)d_out;           // [B, 65] fp32

    int B = in_sizes[1];
    int M = in_sizes[0] / B;

    // Zero the whole output buffer (harness poisons it to 0xAA), coalesced.
    fill_zero_kernel<<<(out_size + 255) / 256, 256>>>(out, out_size);

    // One thread per batch row.
    c4_printf_kernel<<<(B + 255) / 256, 256>>>(mem, addr, outp, out, B, M);
}

// round 3
// speedup vs baseline: 1.5598x; 1.5598x over previous
#include <cuda_runtime.h>

// ---------------------------------------------------------------------------
// Warp-per-row formulation.
//
// Math facts carried over from R2 (verified, rel_err 2.7e-6):
//  * eq_gate over integer indices is an exact one-hot under tanh-saturation,
//    so value = |memory[b, addr[b]]| bitwise.
//  * A digit-gate term q*lo*up is EXACTLY 0.0f unless both gate args > -1.5
//    (tanh saturates to -1.0f -> silu == 0.0f). Live window per pos:
//    q in [max(0, floor((v-1.3)/d)-1), min(qmax, floor((v+2.3)/d)+1)],
//    width <= 7 at pos 0 and <= 4 at pos 1..5.
//  * Summation of the window in ascending q (and count terms in ascending i)
//    reproduces the reference reduction order exactly (adding exact zeros is
//    a no-op for nonnegative accumulators).
//
// New in R3: one warp per batch row; each lane owns one gate term; pos-leader
// lanes 0..5 reduce their window via ascending-order shfl; lane 6 reduces the
// digit count; lane 0 assembles/scatters tokens. Zero-fill is fused (lanes
// zero cols 0..63 before token writes). Single kernel launch.
// ---------------------------------------------------------------------------

static __device__ __forceinline__ float sig_ref(float z) {
    return __fadd_rn(__fmul_rn(0.5f, tanhf(__fmul_rn(0.5f, z))), 0.5f);
}
static __device__ __forceinline__ float silu_ref(float z) {
    return __fmul_rn(z, sig_ref(z));
}
// silu_threshold(x) = (silu(20x + 10) - silu(20x - 10)) / 20
static __device__ __forceinline__ float st_ref(float x) {
    float d = __fmul_rn(20.0f, x);
    float a = silu_ref(__fadd_rn(d, 10.0f));
    float b = silu_ref(__fsub_rn(d, 10.0f));
    return __fdiv_rn(__fsub_rn(a, b), 20.0f);
}

__global__ void __launch_bounds__(256)
c4_printf_warp_kernel(const float* __restrict__ mem,
                      const int*   __restrict__ addr,
                      const int*   __restrict__ outp,
                      float*       __restrict__ out,
                      int B, int M) {
    const unsigned FULL = 0xFFFFFFFFu;
    int warp  = (blockIdx.x * blockDim.x + threadIdx.x) >> 5;
    int lane  = threadIdx.x & 31;
    if (warp >= B) return;
    const int b = warp;

    // --- gather attended value (exact one-hot) and broadcast ----------------
    float v = 0.0f;
    int   op = 0;
    if (lane == 0) {
        int a = addr[b];
        v  = fabsf(__ldg(mem + (long long)b * M + a));
        op = outp[b];
    }
    v = __shfl_sync(FULL, v, 0);

    // --- fused zero-fill of this row's 64 token slots -----------------------
    float* orow = out + (long long)b * 65;
    orow[lane]      = 0.0f;
    orow[lane + 32] = 0.0f;

    // --- per-lane gate term --------------------------------------------------
    // lanes 0..6   : pos 0, window offsets 0..6
    // lanes 7..26  : pos 1..5, window offsets 0..3 (4 lanes per pos)
    // lanes 27..31 : count terms i = 1..5
    float term = 0.0f;
    if (lane >= 27) {
        // st(v - 10^i + 0.5), i = lane - 26
        const float ptab[6] = {1.f, 10.f, 100.f, 1000.f, 10000.f, 100000.f};
        float p = ptab[lane - 26];
        term = st_ref(__fadd_rn(__fsub_rn(v, p), 0.5f));
    } else {
        int pos, off;
        if (lane < 7) { pos = 0;                   off = lane; }
        else          { pos = 1 + ((lane - 7) >> 2); off = (lane - 7) & 3; }
        const float dtab[6]    = {1.f, 10.f, 100.f, 1000.f, 10000.f, 100000.f};
        const int   qmaxtab[6] = {999, 101, 11, 2, 1, 1};
        float d    = dtab[pos];
        int   qmax = qmaxtab[pos];
        int qlo = (int)floorf((v - 1.3f) / d) - 1;
        int qhi = (int)floorf((v + 2.3f) / d) + 1;
        if (qlo < 0)    qlo = 0;
        if (qhi > qmax) qhi = qmax;
        int q = qlo + off;
        if (q <= qhi) {
            float qf = (float)q;
            // lower = st(v - q*d + 0.5), upper = st((q+1)*d - v - 0.5)
            float lo_arg = __fadd_rn(__fsub_rn(v, __fmul_rn(qf, d)), 0.5f);
            float up_arg = __fsub_rn(
                __fsub_rn(__fmul_rn(__fadd_rn(qf, 1.0f), d), v), 0.5f);
            term = __fmul_rn(__fmul_rn(st_ref(lo_arg), st_ref(up_arg)), qf);
        }
    }

    // --- ascending-order reductions (leaders: lanes 0..5 digits, 6 count) ---
    int base = 0, width = 0;
    if (lane == 0)      { base = 0;                 width = 7; }
    else if (lane < 6)  { base = 7 + (lane - 1) * 4; width = 4; }
    else if (lane == 6) { base = 27;                width = 5; }
    float acc = 0.0f;
    #pragma unroll
    for (int k = 0; k < 7; ++k) {
        int src = base + k;
        float t = __shfl_sync(FULL, term, src < 32 ? src : 0);
        if (k < width) acc = __fadd_rn(acc, t);
    }

    // digits on lanes 0..5: floor(quot - floor(quot/10)*10)
    float dg = floorf(__fsub_rn(
        acc, __fmul_rn(floorf(__fdiv_rn(acc, 10.0f)), 10.0f)));
    // count on lane 6: n = floor(1 + sum)
    float cnt = __fadd_rn(1.0f, acc);

    int n = (int)floorf(__shfl_sync(FULL, cnt, 6));
    float digits[6];
    #pragma unroll
    for (int p = 0; p < 6; ++p) digits[p] = __shfl_sync(FULL, dg, p);

    __syncwarp(FULL);  // order zero-fill stores before token scatter

    if (lane == 0) {
        #pragma unroll
        for (int j = 0; j <= 6; ++j) {
            if (j <= n) {
                float tok;
                if (j < n) {
                    int pi = n - 1 - j;
                    pi = pi < 0 ? 0 : (pi > 5 ? 5 : pi);
                    tok = __fadd_rn(48.0f, digits[pi]);
                } else {
                    tok = 10.0f;
                }
                int wp = op + j;
                if (wp >= 0 && wp < 64) orow[wp] = tok;
            }
        }
        orow[64] = v;  // appended value column
    }
}

extern "C" void kernel_launch(void* const* d_in, const int* in_sizes, int n_in,
                              void* d_out, int out_size) {
    const float* mem  = (const float*)d_in[0];   // [B, M] fp32
    const int*   addr = (const int*)d_in[1];     // [B] int32
    const int*   outp = (const int*)d_in[2];     // [B] int32
    float*       out  = (float*)d_out;           // [B, 65] fp32

    int B = in_sizes[1];
    int M = in_sizes[0] / B;

    // One warp per row; 8 warps per block.
    int threads = 256;
    int warps_per_block = threads / 32;
    int blocks = (B + warps_per_block - 1) / warps_per_block;
    c4_printf_warp_kernel<<<blocks, threads>>>(mem, addr, outp, out, B, M);
}